// round 6
// baseline (speedup 1.0000x reference)
#include <cuda_runtime.h>
#include <cuda_bf16.h>
#include <math.h>

#define H 256
#define A_TOT 262144
#define A_MAP 131072
#define NH 4

// ---------------- scratch (device globals; no allocation allowed) ----------------
__device__ float g_keys[(size_t)A_TOT * H];          // 256 MB
__device__ float g_scores[NH * A_TOT];               // 4 MB
__device__ float g_logits[A_TOT];                    // 1 MB
__device__ float g_W1bT_map[H * H];
__device__ float g_W1bT_sch[H * H];
__device__ float g_qpu_contrib[64 * H];
__device__ float g_time_contrib[1000 * H];
__device__ float g_gsum[H];
__device__ float g_U[NH * H];
__device__ float g_c[NH];
__device__ float g_attn_out[H];
__device__ float g_cvec[NH * H];
__device__ float g_expsum[NH];
__device__ unsigned g_smax[NH];
__device__ unsigned g_lmax;
__device__ float g_lsum;

// plain bf16 weight images [256 n][256 k] row-major, hi and lo parts
__device__ __nv_bfloat16 g_W1m_hi[H * H];
__device__ __nv_bfloat16 g_W1m_lo[H * H];
__device__ __nv_bfloat16 g_W1s_hi[H * H];
__device__ __nv_bfloat16 g_W1s_lo[H * H];
__device__ __nv_bfloat16 g_W2m_hi[H * H];
__device__ __nv_bfloat16 g_W2m_lo[H * H];
__device__ __nv_bfloat16 g_W2s_hi[H * H];
__device__ __nv_bfloat16 g_W2s_lo[H * H];

// ---------------- helpers ----------------
__device__ __forceinline__ unsigned f2ord(float f) {
    unsigned u = __float_as_uint(f);
    return (u & 0x80000000u) ? ~u : (u | 0x80000000u);
}
__device__ __forceinline__ float ord2f(unsigned u) {
    u = (u & 0x80000000u) ? (u ^ 0x80000000u) : ~u;
    return __uint_as_float(u);
}
__device__ __forceinline__ unsigned smem_u32(const void* p) {
    unsigned a;
    asm("{ .reg .u64 t; cvta.to.shared.u64 t, %1; cvt.u32.u64 %0, t; }" : "=r"(a) : "l"(p));
    return a;
}
__device__ __forceinline__ void cvt_hilo(float x, unsigned short& h, unsigned short& l) {
    __nv_bfloat16 hb = __float2bfloat16_rn(x);
    float r = x - __bfloat162float(hb);
    h = __bfloat16_as_ushort(hb);
    l = __bfloat16_as_ushort(__float2bfloat16_rn(r));
}

__device__ __forceinline__ void ldsm4(unsigned* r, unsigned addr) {
    asm volatile("ldmatrix.sync.aligned.m8n8.x4.shared.b16 {%0,%1,%2,%3}, [%4];"
        : "=r"(r[0]), "=r"(r[1]), "=r"(r[2]), "=r"(r[3]) : "r"(addr));
}
__device__ __forceinline__ void mma16816(float* c, unsigned a0, unsigned a1, unsigned a2, unsigned a3,
                                         unsigned b0, unsigned b1) {
    asm volatile(
        "mma.sync.aligned.m16n8k16.row.col.f32.bf16.bf16.f32 "
        "{%0,%1,%2,%3}, {%4,%5,%6,%7}, {%8,%9}, {%0,%1,%2,%3};"
        : "+f"(c[0]), "+f"(c[1]), "+f"(c[2]), "+f"(c[3])
        : "r"(a0), "r"(a1), "r"(a2), "r"(a3), "r"(b0), "r"(b1));
}
__device__ __forceinline__ void cp_wait0() { asm volatile("cp.async.wait_group 0;" ::: "memory"); }

// ---------------- SMEM layout (bytes from dynamic smem base) ---------------------
#define AS 264                      /* A row stride (bf16 elems) */
#define A_HI_OFF   0                /* 64 x 264 bf16 = 33792 */
#define A_LO_OFF   33792
#define B_OFF      67584            /* 2 bufs x (hi+lo) x 128 x 72 bf16 = 73728 */
#define B_BUFSZ    36864
#define B_MATSZ    18432
#define BS 72                       /* B row stride (bf16 elems) */
#define KC_OFF     141312           /* contrib (layer1) / keys (epi2): 64 x 260 f32 = 66560 */
#define CS 260
#define ST_OFF     207872
#define ST_B1      0
#define ST_B2      1024
#define ST_U       2048
#define ST_C       6144
#define ST_IDX1    6160
#define ST_IDX2    6416
#define ST_SMX     6672
#define DYN_SMEM   (ST_OFF + 6688)

// ---------------- init ----------------
__global__ void k_init() {
    int t = threadIdx.x;
    if (t < H) g_gsum[t] = 0.0f;
    if (t < NH * H) g_cvec[t] = 0.0f;
    if (t < NH) { g_expsum[t] = 0.0f; g_smax[t] = 0x007FFFFFu; }
    if (t == 0) { g_lsum = 0.0f; g_lmax = 0x007FFFFFu; }
}

// ---------------- weight prep: fp32 W -> plain bf16 hi/lo images -----------------
__global__ void k_wprep(const float* __restrict__ mapW1, const float* __restrict__ schW1,
                        const float* __restrict__ mapW2, const float* __restrict__ schW2) {
    int mat = blockIdx.x >> 8, n = blockIdx.x & 255;
    const float* src; __nv_bfloat16 *dhi, *dlo; int ld;
    switch (mat) {
        case 0: src = mapW1; ld = 512; dhi = g_W1m_hi; dlo = g_W1m_lo; break;
        case 1: src = schW1; ld = 512; dhi = g_W1s_hi; dlo = g_W1s_lo; break;
        case 2: src = mapW2; ld = 256; dhi = g_W2m_hi; dlo = g_W2m_lo; break;
        default: src = schW2; ld = 256; dhi = g_W2s_hi; dlo = g_W2s_lo; break;
    }
    int k = threadIdx.x * 4;
    float4 v = *(const float4*)(src + (size_t)n * ld + k);
    unsigned short h0, l0, h1, l1, h2, l2, h3, l3;
    cvt_hilo(v.x, h0, l0); cvt_hilo(v.y, h1, l1);
    cvt_hilo(v.z, h2, l2); cvt_hilo(v.w, h3, l3);
    *(uint2*)(dhi + n * 256 + k) = make_uint2((unsigned)h0 | ((unsigned)h1 << 16), (unsigned)h2 | ((unsigned)h3 << 16));
    *(uint2*)(dlo + n * 256 + k) = make_uint2((unsigned)l0 | ((unsigned)l1 << 16), (unsigned)l2 | ((unsigned)l3 << 16));
}

// ---------------- transpose W1b halves (k-major, for k_contrib) ------------------
__global__ void k_transpose(const float* __restrict__ mapW1, const float* __restrict__ schW1) {
    __shared__ float s[32][33];
    const float* src = blockIdx.y ? schW1 : mapW1;
    float* dst = blockIdx.y ? g_W1bT_sch : g_W1bT_map;
    int k0 = (blockIdx.x & 7) * 32;
    int n0 = (blockIdx.x >> 3) * 32;
    int tx = threadIdx.x, ty = threadIdx.y;
#pragma unroll
    for (int i = 0; i < 32; i += 8)
        s[ty + i][tx] = src[(size_t)(n0 + ty + i) * 512 + 256 + k0 + tx];
    __syncthreads();
#pragma unroll
    for (int i = 0; i < 32; i += 8)
        dst[(size_t)(k0 + ty + i) * H + n0 + tx] = s[tx][ty + i];
}

// ---------------- g = mean(all_embeddings) ---------------------------------------
__global__ void k_mean(const float* __restrict__ all_emb) {
    int t = threadIdx.x;
    size_t base = (size_t)blockIdx.x * 256;
    float s = 0.0f;
    for (int r = 0; r < 256; r++) s += all_emb[(base + r) * H + t];
    atomicAdd(&g_gsum[t], s);
}

// ---------------- small-table layer-1 contributions (qpu / time) -----------------
__global__ void k_contrib(const float* __restrict__ qpu_emb, const float* __restrict__ time_tab) {
    __shared__ float e_s[16 * H];
    int b = blockIdx.x, t = threadIdx.x;
    const float* E; const float* WT; float* out; int base, total;
    if (b < 4) { E = qpu_emb; WT = g_W1bT_map; out = g_qpu_contrib; base = b * 16; total = 64; }
    else { E = time_tab; WT = g_W1bT_sch; out = g_time_contrib; base = (b - 4) * 16; total = 1000; }
    int nrows = total - base; if (nrows > 16) nrows = 16;
    for (int i = 0; i < nrows; i++) e_s[i * H + t] = E[(size_t)(base + i) * H + t];
    __syncthreads();
    float acc[16];
#pragma unroll
    for (int i = 0; i < 16; i++) acc[i] = 0.0f;
    for (int k = 0; k < H; k++) {
        float w = WT[(size_t)k * H + t];
#pragma unroll
        for (int i = 0; i < 16; i++) acc[i] += e_s[i * H + k] * w;
    }
    for (int i = 0; i < nrows; i++) out[(size_t)(base + i) * H + t] = acc[i];
}

// ---------------- query MLP + fold attention Q/K into U, c -----------------------
__global__ void k_small(const float* __restrict__ qgW1, const float* __restrict__ qgb1,
                        const float* __restrict__ qgW2, const float* __restrict__ qgb2,
                        const float* __restrict__ Wq,   const float* __restrict__ bq,
                        const float* __restrict__ Wk,   const float* __restrict__ bk) {
    __shared__ float g_s[H], h_s[H], qy_s[H], q_s[H];
    int t = threadIdx.x;
    g_s[t] = g_gsum[t] * (1.0f / 131072.0f);
    __syncthreads();
    float acc = qgb1[t];
    for (int k = 0; k < H; k++) acc += g_s[k] * qgW1[t * H + k];
    h_s[t] = fmaxf(acc, 0.0f);
    __syncthreads();
    acc = qgb2[t];
    for (int k = 0; k < H; k++) acc += h_s[k] * qgW2[t * H + k];
    qy_s[t] = acc;
    __syncthreads();
    acc = bq[t];
    for (int k = 0; k < H; k++) acc += qy_s[k] * Wq[t * H + k];
    q_s[t] = acc;
    __syncthreads();
#pragma unroll
    for (int hh = 0; hh < NH; hh++) {
        float u = 0.0f;
        for (int d = 0; d < 64; d++) u += q_s[hh * 64 + d] * Wk[(hh * 64 + d) * H + t];
        g_U[hh * H + t] = u * 0.125f;
    }
    if (t < NH) {
        float c = 0.0f;
        for (int d = 0; d < 64; d++) c += q_s[t * 64 + d] * bk[t * 64 + d];
        g_c[t] = c * 0.125f;
    }
}

// ---------------- cp.async chunk copy: [128n x 64k] hi+lo -> B ring buffer -------
__device__ __forceinline__ void issue_chunk(const __nv_bfloat16* imgHi, const __nv_bfloat16* imgLo,
                                            int chunk, unsigned bufB, int tid) {
    int nh = chunk >> 2, kc = chunk & 3;
#pragma unroll
    for (int i = 0; i < 8; i++) {
        int flat = i * 256 + tid;                // 0..2047
        int mat = flat >> 10;                    // 0 = hi, 1 = lo
        int rem = flat & 1023;
        int n = rem >> 3, c = rem & 7;
        const __nv_bfloat16* src = (mat ? imgLo : imgHi) + (nh * 128 + n) * 256 + kc * 64 + c * 8;
        unsigned dst = bufB + mat * B_MATSZ + (n * BS + c * 8) * 2;
        asm volatile("cp.async.cg.shared.global [%0], [%1], 16;" :: "r"(dst), "l"(src));
    }
    asm volatile("cp.async.commit_group;" ::: "memory");
}

// ---------------- one MLP layer: D[64,256] += A(hi+lo)[64,256] @ W(hi+lo)^T ------
__device__ __forceinline__ void run_layer(float (&acc)[2][2][4][4],
                                          const __nv_bfloat16* imgHi, const __nv_bfloat16* imgLo,
                                          unsigned aHiL, unsigned aLoL, unsigned bL,
                                          unsigned sbB, int tid) {
#pragma unroll 1
    for (int i = 0; i < 8; i++) {
        int nh = i >> 2;
        cp_wait0();
        __syncthreads();
        if (i < 7) issue_chunk(imgHi, imgLo, i + 1, sbB + ((i + 1) & 1) * B_BUFSZ, tid);
        unsigned bufB = sbB + (i & 1) * B_BUFSZ;
        int kcbase = (i & 3) * 64;
#pragma unroll
        for (int ks = 0; ks < 4; ks++) {
            int kg = kcbase + ks * 16;
            unsigned Ah0[4], Ah1[4], Al0[4], Al1[4], Bh[8], Bl[8];
            ldsm4(Ah0, aHiL + kg * 2);
            ldsm4(Ah1, aHiL + kg * 2 + 16 * AS * 2);
            ldsm4(Al0, aLoL + kg * 2);
            ldsm4(Al1, aLoL + kg * 2 + 16 * AS * 2);
            unsigned bo = bufB + bL + ks * 16 * 2;
            ldsm4(Bh + 0, bo);
            ldsm4(Bh + 4, bo + 16 * BS * 2);
            ldsm4(Bl + 0, bo + B_MATSZ);
            ldsm4(Bl + 4, bo + B_MATSZ + 16 * BS * 2);
#pragma unroll
            for (int mt = 0; mt < 2; mt++) {
                unsigned* Ah = mt ? Ah1 : Ah0;
                unsigned* Al = mt ? Al1 : Al0;
#pragma unroll
                for (int nt = 0; nt < 4; nt++) {
                    unsigned bh0 = Bh[(nt >> 1) * 4 + (nt & 1)];
                    unsigned bh1 = Bh[(nt >> 1) * 4 + (nt & 1) + 2];
                    unsigned bl0 = Bl[(nt >> 1) * 4 + (nt & 1)];
                    unsigned bl1 = Bl[(nt >> 1) * 4 + (nt & 1) + 2];
                    float* c = acc[nh][mt][nt];
                    mma16816(c, Ah[0], Ah[1], Ah[2], Ah[3], bh0, bh1);
                    mma16816(c, Al[0], Al[1], Al[2], Al[3], bh0, bh1);
                    mma16816(c, Ah[0], Ah[1], Ah[2], Ah[3], bl0, bl1);
                }
            }
        }
    }
}

// ---------------- main fused kernel -----------------------------------------------
__global__ __launch_bounds__(256, 1)
void k_mlp_main(const float* __restrict__ qubit_emb, const float* __restrict__ gate_emb,
                const int* __restrict__ map_qubit, const int* __restrict__ map_qpu,
                const int* __restrict__ sched_gate, const int* __restrict__ sched_time,
                const float* __restrict__ map_b1, const float* __restrict__ map_b2,
                const float* __restrict__ sch_b1, const float* __restrict__ sch_b2) {
    extern __shared__ unsigned char smem[];
    char* basep = (char*)smem;
    unsigned sb = smem_u32(smem);

    int tid = threadIdx.x;
    int lane = tid & 31, w = tid >> 5;
    int m_base = (w & 1) * 32;
    int n_base = (w >> 1) * 32;
    int rowbase = blockIdx.x * 64;
    bool is_map = rowbase < A_MAP;
    int lr0 = is_map ? rowbase : rowbase - A_MAP;
    const float* emb = is_map ? qubit_emb : gate_emb;
    const int* idx1g = is_map ? map_qubit : sched_gate;
    const int* idx2g = is_map ? map_qpu : sched_time;
    const float* contrib = is_map ? g_qpu_contrib : g_time_contrib;
    const float* b1 = is_map ? map_b1 : sch_b1;
    const float* b2 = is_map ? map_b2 : sch_b2;
    const __nv_bfloat16* img1hi = is_map ? g_W1m_hi : g_W1s_hi;
    const __nv_bfloat16* img1lo = is_map ? g_W1m_lo : g_W1s_lo;
    const __nv_bfloat16* img2hi = is_map ? g_W2m_hi : g_W2s_hi;
    const __nv_bfloat16* img2lo = is_map ? g_W2m_lo : g_W2s_lo;

    int* idx1_s = (int*)(basep + ST_OFF + ST_IDX1);
    int* idx2_s = (int*)(basep + ST_OFF + ST_IDX2);
    float* b1_s = (float*)(basep + ST_OFF + ST_B1);
    float* b2_s = (float*)(basep + ST_OFF + ST_B2);
    float* U_s  = (float*)(basep + ST_OFF + ST_U);
    float* c_s  = (float*)(basep + ST_OFF + ST_C);
    unsigned* smx_s = (unsigned*)(basep + ST_OFF + ST_SMX);
    float* kc_s = (float*)(basep + KC_OFF);     // contrib, later keys staging

    // prefetch layer-1 chunk 0 immediately (no dependencies)
    issue_chunk(img1hi, img1lo, 0, sb + B_OFF, tid);

    if (tid < 64) { idx1_s[tid] = idx1g[lr0 + tid]; idx2_s[tid] = idx2g[lr0 + tid]; }
    b1_s[tid] = b1[tid];
    b2_s[tid] = b2[tid];
#pragma unroll
    for (int i = 0; i < 4; i++) U_s[i * 256 + tid] = g_U[i * 256 + tid];
    if (tid < NH) c_s[tid] = g_c[tid];
    if (tid < NH) smx_s[tid] = 0x007FFFFFu;
    __syncthreads();

    // gather X [64 x 256] fp32 -> split into A hi/lo smem
#pragma unroll 1
    for (int i = 0; i < 16; i++) {
        int flat = i * 256 + tid;      // 64 rows x 64 float4
        int r = flat >> 6, c4 = flat & 63;
        float4 v = ((const float4*)(emb + (size_t)idx1_s[r] * H))[c4];
        unsigned short h0, l0, h1, l1, h2, l2, h3, l3;
        cvt_hilo(v.x, h0, l0); cvt_hilo(v.y, h1, l1);
        cvt_hilo(v.z, h2, l2); cvt_hilo(v.w, h3, l3);
        unsigned off = (unsigned)(r * AS + c4 * 4) * 2;
        *(uint2*)(basep + A_HI_OFF + off) = make_uint2((unsigned)h0 | ((unsigned)h1 << 16), (unsigned)h2 | ((unsigned)h3 << 16));
        *(uint2*)(basep + A_LO_OFF + off) = make_uint2((unsigned)l0 | ((unsigned)l1 << 16), (unsigned)l2 | ((unsigned)l3 << 16));
        // gather contrib rows into kc_s (stride 260)
        float4 cv = ((const float4*)(contrib + (size_t)idx2_s[r] * H))[c4];
        *(float4*)(kc_s + r * CS + c4 * 4) = cv;
    }
    __syncthreads();

    // lane-based ldmatrix base addresses
    int g8 = lane >> 3, lr = lane & 7;
    int arow = m_base + lr + ((g8 & 1) ? 8 : 0);
    int acol = (g8 & 2) ? 8 : 0;
    unsigned aHiL = sb + A_HI_OFF + (unsigned)(arow * AS + acol) * 2;
    unsigned aLoL = sb + A_LO_OFF + (unsigned)(arow * AS + acol) * 2;
    int brow = n_base + lr + ((g8 & 1) ? 8 : 0);
    unsigned bL = (unsigned)(brow * BS + acol) * 2;

    float acc[2][2][4][4];
#pragma unroll
    for (int a = 0; a < 2; a++)
#pragma unroll
        for (int b = 0; b < 2; b++)
#pragma unroll
            for (int c = 0; c < 4; c++)
#pragma unroll
                for (int d = 0; d < 4; d++) acc[a][b][c][d] = 0.0f;

    // ---- layer 1 ----
    run_layer(acc, img1hi, img1lo, aHiL, aLoL, bL, sb + B_OFF, tid);
    __syncthreads();

    // prefetch layer-2 chunk 0 (overlaps epilogue 1)
    issue_chunk(img2hi, img2lo, 0, sb + B_OFF, tid);

    // ---- epilogue 1: h = relu(D + contrib + b1) -> back into A hi/lo ------------
#pragma unroll
    for (int nh = 0; nh < 2; nh++)
#pragma unroll
        for (int mt = 0; mt < 2; mt++)
#pragma unroll
            for (int nt = 0; nt < 4; nt++)
#pragma unroll
                for (int hl = 0; hl < 2; hl++) {
                    int row = m_base + mt * 16 + (lane >> 2) + hl * 8;
                    int col = nh * 128 + n_base + nt * 8 + 2 * (lane & 3);
                    float v0 = acc[nh][mt][nt][hl * 2 + 0] + kc_s[row * CS + col] + b1_s[col];
                    float v1 = acc[nh][mt][nt][hl * 2 + 1] + kc_s[row * CS + col + 1] + b1_s[col + 1];
                    v0 = fmaxf(v0, 0.0f); v1 = fmaxf(v1, 0.0f);
                    unsigned short h0, l0, h1, l1;
                    cvt_hilo(v0, h0, l0); cvt_hilo(v1, h1, l1);
                    unsigned off = (unsigned)(row * AS + col) * 2;
                    *(unsigned*)(basep + A_HI_OFF + off) = (unsigned)h0 | ((unsigned)h1 << 16);
                    *(unsigned*)(basep + A_LO_OFF + off) = (unsigned)l0 | ((unsigned)l1 << 16);
                    acc[nh][mt][nt][hl * 2 + 0] = 0.0f;
                    acc[nh][mt][nt][hl * 2 + 1] = 0.0f;
                }
    __syncthreads();

    // ---- layer 2 ----
    run_layer(acc, img2hi, img2lo, aHiL, aLoL, bL, sb + B_OFF, tid);
    __syncthreads();

    // ---- epilogue 2: keys = D + b2 -> stage in smem ------------------------------
#pragma unroll
    for (int nh = 0; nh < 2; nh++)
#pragma unroll
        for (int mt = 0; mt < 2; mt++)
#pragma unroll
            for (int nt = 0; nt < 4; nt++)
#pragma unroll
                for (int hl = 0; hl < 2; hl++) {
                    int row = m_base + mt * 16 + (lane >> 2) + hl * 8;
                    int col = nh * 128 + n_base + nt * 8 + 2 * (lane & 3);
                    float v0 = acc[nh][mt][nt][hl * 2 + 0] + b2_s[col];
                    float v1 = acc[nh][mt][nt][hl * 2 + 1] + b2_s[col + 1];
                    kc_s[row * CS + col] = v0;
                    kc_s[row * CS + col + 1] = v1;
                }
    __syncthreads();

    // coalesced keys write
#pragma unroll 1
    for (int i = 0; i < 16; i++) {
        int flat = i * 256 + tid;
        int r = flat >> 6, c4 = flat & 63;
        float4 v = *(const float4*)(kc_s + r * CS + c4 * 4);
        *(float4*)(g_keys + (size_t)(rowbase + r) * H + c4 * 4) = v;
    }

    // score dots: thread t -> (row = t>>2, head = t&3)
    {
        int r = tid >> 2, hh = tid & 3;
        float s = c_s[hh];
#pragma unroll 1
        for (int c = 0; c < 256; c += 4) {
            float4 kv = *(const float4*)(kc_s + r * CS + c);
            float4 uv = *(const float4*)(U_s + hh * 256 + c);
            s += kv.x * uv.x + kv.y * uv.y + kv.z * uv.z + kv.w * uv.w;
        }
        g_scores[(size_t)hh * A_TOT + rowbase + r] = s;
        atomicMax(&smx_s[hh], f2ord(s));
    }
    __syncthreads();
    if (tid < NH) atomicMax(&g_smax[tid], smx_s[tid]);
}

// ---------------- pass 2: softmax weights, weighted key-sum (cvec), expsum -------
__global__ void k_attn_acc() {
    __shared__ float w_s[NH * 256];
    __shared__ float red_s[NH * 8];
    int tid = threadIdx.x;
    size_t base = (size_t)blockIdx.x * 256;
    float sm[NH];
#pragma unroll
    for (int hh = 0; hh < NH; hh++) sm[hh] = ord2f(g_smax[hh]);
    float es[NH];
#pragma unroll
    for (int hh = 0; hh < NH; hh++) {
        float s = g_scores[(size_t)hh * A_TOT + base + tid];
        float w = __expf(s - sm[hh]);
        w_s[hh * 256 + tid] = w;
        es[hh] = w;
    }
    __syncthreads();
    float cv0 = 0, cv1 = 0, cv2 = 0, cv3 = 0;
    for (int r = 0; r < 256; r++) {
        float kj = g_keys[(base + r) * H + tid];
        cv0 += w_s[r] * kj;
        cv1 += w_s[256 + r] * kj;
        cv2 += w_s[512 + r] * kj;
        cv3 += w_s[768 + r] * kj;
    }
    atomicAdd(&g_cvec[0 * H + tid], cv0);
    atomicAdd(&g_cvec[1 * H + tid], cv1);
    atomicAdd(&g_cvec[2 * H + tid], cv2);
    atomicAdd(&g_cvec[3 * H + tid], cv3);
#pragma unroll
    for (int hh = 0; hh < NH; hh++)
        for (int off = 16; off; off >>= 1) es[hh] += __shfl_down_sync(0xffffffffu, es[hh], off);
    if ((tid & 31) == 0) {
        int w = tid >> 5;
#pragma unroll
        for (int hh = 0; hh < NH; hh++) red_s[hh * 8 + w] = es[hh];
    }
    __syncthreads();
    if (tid < NH) {
        float s = 0.0f;
#pragma unroll
        for (int w = 0; w < 8; w++) s += red_s[tid * 8 + w];
        atomicAdd(&g_expsum[tid], s);
    }
}

// ---------------- ctx -> attn_out ------------------------------------------------
__global__ void k_ctx(const float* __restrict__ Wv, const float* __restrict__ bv,
                      const float* __restrict__ Wo, const float* __restrict__ bo) {
    __shared__ float ctx_s[H];
    int t = threadIdx.x;
    int hh = t >> 6;
    float inv = 1.0f / g_expsum[hh];
    float acc = 0.0f;
    for (int j = 0; j < H; j++) acc += Wv[t * H + j] * g_cvec[hh * H + j];
    ctx_s[t] = acc * inv + bv[t];
    __syncthreads();
    float o = bo[t];
    for (int j = 0; j < H; j++) o += Wo[t * H + j] * ctx_s[j];
    g_attn_out[t] = o;
}

// ---------------- logits = keys @ attn_out, track max ----------------------------
__global__ void k_logits() {
    __shared__ float ao_s[H];
    __shared__ float m_s[64];
    int tid = threadIdx.x;
    ao_s[tid] = g_attn_out[tid];
    __syncthreads();
    int r = tid >> 2, q4 = tid & 3;
    size_t a = (size_t)blockIdx.x * 64 + r;
    const float4* kp = (const float4*)(g_keys + a * H + q4 * 64);
    const float4* ap = (const float4*)(ao_s + q4 * 64);
    float p = 0.0f;
#pragma unroll
    for (int u = 0; u < 16; u++) {
        float4 kv = kp[u];
        float4 av = ap[u];
        p += kv.x * av.x + kv.y * av.y + kv.z * av.z + kv.w * av.w;
    }
    p += __shfl_down_sync(0xffffffffu, p, 2);
    p += __shfl_down_sync(0xffffffffu, p, 1);
    if (q4 == 0) { g_logits[a] = p; m_s[r] = p; }
    __syncthreads();
    if (tid < 32) {
        float m = fmaxf(m_s[tid], m_s[tid + 32]);
        for (int off = 16; off; off >>= 1) m = fmaxf(m, __shfl_down_sync(0xffffffffu, m, off));
        if (tid == 0) atomicMax(&g_lmax, f2ord(m));
    }
}

// ---------------- softmax denominator over logits --------------------------------
__global__ void k_lsum() {
    __shared__ float r_s[256];
    float lmax = ord2f(g_lmax);
    float s = 0.0f;
    for (int i = blockIdx.x * 256 + threadIdx.x; i < A_TOT; i += 256 * 256)
        s += __expf(g_logits[i] - lmax);
    r_s[threadIdx.x] = s;
    __syncthreads();
    for (int off = 128; off; off >>= 1) {
        if (threadIdx.x < off) r_s[threadIdx.x] += r_s[threadIdx.x + off];
        __syncthreads();
    }
    if (threadIdx.x == 0) atomicAdd(&g_lsum, r_s[0]);
}

// ---------------- write probs (+ logits) to output -------------------------------
__global__ void k_probs(float* __restrict__ out, int write_logits) {
    int i = blockIdx.x * 256 + threadIdx.x;
    float lmax = ord2f(g_lmax);
    float l = g_logits[i];
    out[i] = __expf(l - lmax) / g_lsum;
    if (write_logits) out[A_TOT + i] = l;
}

// ---------------- launch ----------------------------------------------------------
extern "C" void kernel_launch(void* const* d_in, const int* in_sizes, int n_in,
                              void* d_out, int out_size) {
    const float* qubit_emb = (const float*)d_in[0];
    const float* qpu_emb   = (const float*)d_in[1];
    const float* gate_emb  = (const float*)d_in[2];
    const float* all_emb   = (const float*)d_in[3];
    const float* time_tab  = (const float*)d_in[4];
    const float* map_W1 = (const float*)d_in[5];
    const float* map_b1 = (const float*)d_in[6];
    const float* map_W2 = (const float*)d_in[7];
    const float* map_b2 = (const float*)d_in[8];
    const float* sch_W1 = (const float*)d_in[9];
    const float* sch_b1 = (const float*)d_in[10];
    const float* sch_W2 = (const float*)d_in[11];
    const float* sch_b2 = (const float*)d_in[12];
    const float* qg_W1 = (const float*)d_in[13];
    const float* qg_b1 = (const float*)d_in[14];
    const float* qg_W2 = (const float*)d_in[15];
    const float* qg_b2 = (const float*)d_in[16];
    const float* attn_Wq = (const float*)d_in[17];
    const float* attn_bq = (const float*)d_in[18];
    const float* attn_Wk = (const float*)d_in[19];
    const float* attn_bk = (const float*)d_in[20];
    const float* attn_Wv = (const float*)d_in[21];
    const float* attn_bv = (const float*)d_in[22];
    const float* attn_Wo = (const float*)d_in[23];
    const float* attn_bo = (const float*)d_in[24];
    const int* map_qubit  = (const int*)d_in[25];
    const int* map_qpu    = (const int*)d_in[26];
    const int* sched_gate = (const int*)d_in[27];
    const int* sched_time = (const int*)d_in[28];
    float* out = (float*)d_out;
    int write_logits = (out_size >= 2 * A_TOT) ? 1 : 0;

    cudaFuncSetAttribute(k_mlp_main, cudaFuncAttributeMaxDynamicSharedMemorySize, DYN_SMEM);

    k_init<<<1, 1024>>>();
    k_wprep<<<1024, 64>>>(map_W1, sch_W1, map_W2, sch_W2);
    k_transpose<<<dim3(64, 2), dim3(32, 8)>>>(map_W1, sch_W1);
    k_mean<<<512, 256>>>(all_emb);
    k_contrib<<<67, 256>>>(qpu_emb, time_tab);
    k_small<<<1, 256>>>(qg_W1, qg_b1, qg_W2, qg_b2, attn_Wq, attn_bq, attn_Wk, attn_bk);
    k_mlp_main<<<4096, 256, DYN_SMEM>>>(qubit_emb, gate_emb, map_qubit, map_qpu,
                                        sched_gate, sched_time,
                                        map_b1, map_b2, sch_b1, sch_b2);
    k_attn_acc<<<1024, 256>>>();
    k_ctx<<<1, 256>>>(attn_Wv, attn_bv, attn_Wo, attn_bo);
    k_logits<<<4096, 256>>>();
    k_lsum<<<256, 256>>>();
    k_probs<<<1024, 256>>>(out, write_logits);
}

// round 8
// speedup vs baseline: 1.5510x; 1.5510x over previous
#include <cuda_runtime.h>
#include <cuda_bf16.h>
#include <math.h>

#define H 256
#define A_TOT 262144
#define A_MAP 131072
#define NH 4

// ---------------- scratch (device globals; no allocation allowed) ----------------
__device__ float g_keys[(size_t)A_TOT * H];          // 256 MB
__device__ float g_scores[NH * A_TOT];               // 4 MB
__device__ float g_logits[A_TOT];                    // 1 MB
__device__ float g_W1bT_map[H * H];
__device__ float g_W1bT_sch[H * H];
__device__ float g_qpu_contrib[64 * H];
__device__ float g_time_contrib[1000 * H];
__device__ float g_gsum[H];
__device__ float g_U[NH * H];
__device__ float g_c[NH];
__device__ float g_attn_out[H];
__device__ float g_cvec[NH * H];
__device__ float g_expsum[NH];
__device__ unsigned g_smax[NH];
__device__ unsigned g_lmax;
__device__ float g_lsum;

// plain bf16 weight images [256 n][256 k] row-major, hi and lo parts
__device__ __nv_bfloat16 g_W1m_hi[H * H];
__device__ __nv_bfloat16 g_W1m_lo[H * H];
__device__ __nv_bfloat16 g_W1s_hi[H * H];
__device__ __nv_bfloat16 g_W1s_lo[H * H];
__device__ __nv_bfloat16 g_W2m_hi[H * H];
__device__ __nv_bfloat16 g_W2m_lo[H * H];
__device__ __nv_bfloat16 g_W2s_hi[H * H];
__device__ __nv_bfloat16 g_W2s_lo[H * H];

// ---------------- helpers ----------------
__device__ __forceinline__ unsigned f2ord(float f) {
    unsigned u = __float_as_uint(f);
    return (u & 0x80000000u) ? ~u : (u | 0x80000000u);
}
__device__ __forceinline__ float ord2f(unsigned u) {
    u = (u & 0x80000000u) ? (u ^ 0x80000000u) : ~u;
    return __uint_as_float(u);
}
__device__ __forceinline__ unsigned smem_u32(const void* p) {
    unsigned a;
    asm("{ .reg .u64 t; cvta.to.shared.u64 t, %1; cvt.u32.u64 %0, t; }" : "=r"(a) : "l"(p));
    return a;
}
__device__ __forceinline__ void cvt_hilo(float x, unsigned short& h, unsigned short& l) {
    __nv_bfloat16 hb = __float2bfloat16_rn(x);
    float r = x - __bfloat162float(hb);
    h = __bfloat16_as_ushort(hb);
    l = __bfloat16_as_ushort(__float2bfloat16_rn(r));
}
__device__ __forceinline__ void ldsm4(unsigned* r, unsigned addr) {
    asm volatile("ldmatrix.sync.aligned.m8n8.x4.shared.b16 {%0,%1,%2,%3}, [%4];"
        : "=r"(r[0]), "=r"(r[1]), "=r"(r[2]), "=r"(r[3]) : "r"(addr));
}
__device__ __forceinline__ void mma16816(float* c, const unsigned* a, unsigned b0, unsigned b1) {
    asm volatile(
        "mma.sync.aligned.m16n8k16.row.col.f32.bf16.bf16.f32 "
        "{%0,%1,%2,%3}, {%4,%5,%6,%7}, {%8,%9}, {%0,%1,%2,%3};"
        : "+f"(c[0]), "+f"(c[1]), "+f"(c[2]), "+f"(c[3])
        : "r"(a[0]), "r"(a[1]), "r"(a[2]), "r"(a[3]), "r"(b0), "r"(b1));
}
__device__ __forceinline__ void cp_wait0() { asm volatile("cp.async.wait_group 0;" ::: "memory"); }

// ---------------- SMEM layout (bytes from dynamic smem base) ---------------------
#define AS 264                      /* A row stride (bf16 elems) */
#define A_HI_OFF   0                /* 128 x 264 x 2B = 67584 */
#define A_LO_OFF   67584
#define B_OFF      135168           /* 2 bufs x (hi+lo) x 256 x 40 bf16 */
#define B_BUFSZ    40960
#define B_MATSZ    20480
#define BS 40                       /* B row stride (bf16 elems); 80B, 16B-aligned */
#define ST_OFF     217088
#define ST_B1      0
#define ST_B2      1024
#define ST_U       2048
#define ST_C       6144
#define ST_IDX1    6176
#define ST_IDX2    6688
#define ST_P       7200             /* 128 rows x 4 heads floats = 2048 */
#define ST_SMX     9248
#define STAT_SZ    9280
#define DYN_SMEM   (ST_OFF + STAT_SZ)   /* 226368 */

// ---------------- weight prep (+ global init folded into block 0) ----------------
__global__ void k_wprep(const float* __restrict__ mapW1, const float* __restrict__ schW1,
                        const float* __restrict__ mapW2, const float* __restrict__ schW2) {
    int tid = threadIdx.x;
    if (blockIdx.x == 0) {
        for (int i = tid; i < NH * H; i += 64) g_cvec[i] = 0.0f;
        for (int i = tid; i < H; i += 64) g_gsum[i] = 0.0f;
        if (tid < NH) { g_expsum[tid] = 0.0f; g_smax[tid] = 0x007FFFFFu; }
        if (tid == 0) { g_lsum = 0.0f; g_lmax = 0x007FFFFFu; }
    }
    int mat = blockIdx.x >> 8, n = blockIdx.x & 255;
    const float* src; __nv_bfloat16 *dhi, *dlo; int ld;
    switch (mat) {
        case 0: src = mapW1; ld = 512; dhi = g_W1m_hi; dlo = g_W1m_lo; break;
        case 1: src = schW1; ld = 512; dhi = g_W1s_hi; dlo = g_W1s_lo; break;
        case 2: src = mapW2; ld = 256; dhi = g_W2m_hi; dlo = g_W2m_lo; break;
        default: src = schW2; ld = 256; dhi = g_W2s_hi; dlo = g_W2s_lo; break;
    }
    int k = tid * 4;
    float4 v = *(const float4*)(src + (size_t)n * ld + k);
    unsigned short h0, l0, h1, l1, h2, l2, h3, l3;
    cvt_hilo(v.x, h0, l0); cvt_hilo(v.y, h1, l1);
    cvt_hilo(v.z, h2, l2); cvt_hilo(v.w, h3, l3);
    *(uint2*)(dhi + n * 256 + k) = make_uint2((unsigned)h0 | ((unsigned)h1 << 16), (unsigned)h2 | ((unsigned)h3 << 16));
    *(uint2*)(dlo + n * 256 + k) = make_uint2((unsigned)l0 | ((unsigned)l1 << 16), (unsigned)l2 | ((unsigned)l3 << 16));
}

// ---------------- transpose W1b halves (k-major, for k_contrib) ------------------
__global__ void k_transpose(const float* __restrict__ mapW1, const float* __restrict__ schW1) {
    __shared__ float s[32][33];
    const float* src = blockIdx.y ? schW1 : mapW1;
    float* dst = blockIdx.y ? g_W1bT_sch : g_W1bT_map;
    int k0 = (blockIdx.x & 7) * 32;
    int n0 = (blockIdx.x >> 3) * 32;
    int tx = threadIdx.x, ty = threadIdx.y;
#pragma unroll
    for (int i = 0; i < 32; i += 8)
        s[ty + i][tx] = src[(size_t)(n0 + ty + i) * 512 + 256 + k0 + tx];
    __syncthreads();
#pragma unroll
    for (int i = 0; i < 32; i += 8)
        dst[(size_t)(k0 + ty + i) * H + n0 + tx] = s[tx][ty + i];
}

// ---------------- g = mean(all_embeddings) ---------------------------------------
__global__ void k_mean(const float* __restrict__ all_emb) {
    int t = threadIdx.x;
    size_t base = (size_t)blockIdx.x * 256;
    float s = 0.0f;
    for (int r = 0; r < 256; r++) s += all_emb[(base + r) * H + t];
    atomicAdd(&g_gsum[t], s);
}

// ---------------- small-table layer-1 contributions (qpu / time) -----------------
__global__ void k_contrib(const float* __restrict__ qpu_emb, const float* __restrict__ time_tab) {
    __shared__ float e_s[16 * H];
    int b = blockIdx.x, t = threadIdx.x;
    const float* E; const float* WT; float* out; int base, total;
    if (b < 4) { E = qpu_emb; WT = g_W1bT_map; out = g_qpu_contrib; base = b * 16; total = 64; }
    else { E = time_tab; WT = g_W1bT_sch; out = g_time_contrib; base = (b - 4) * 16; total = 1000; }
    int nrows = total - base; if (nrows > 16) nrows = 16;
    for (int i = 0; i < nrows; i++) e_s[i * H + t] = E[(size_t)(base + i) * H + t];
    __syncthreads();
    float acc[16];
#pragma unroll
    for (int i = 0; i < 16; i++) acc[i] = 0.0f;
    for (int k = 0; k < H; k++) {
        float w = WT[(size_t)k * H + t];
#pragma unroll
        for (int i = 0; i < 16; i++) acc[i] += e_s[i * H + k] * w;
    }
    for (int i = 0; i < nrows; i++) out[(size_t)(base + i) * H + t] = acc[i];
}

// ---------------- query MLP + fold attention Q/K into U, c -----------------------
__global__ void k_small(const float* __restrict__ qgW1, const float* __restrict__ qgb1,
                        const float* __restrict__ qgW2, const float* __restrict__ qgb2,
                        const float* __restrict__ Wq,   const float* __restrict__ bq,
                        const float* __restrict__ Wk,   const float* __restrict__ bk) {
    __shared__ float g_s[H], h_s[H], qy_s[H], q_s[H];
    int t = threadIdx.x;
    g_s[t] = g_gsum[t] * (1.0f / 131072.0f);
    __syncthreads();
    float acc = qgb1[t];
    for (int k = 0; k < H; k++) acc += g_s[k] * qgW1[t * H + k];
    h_s[t] = fmaxf(acc, 0.0f);
    __syncthreads();
    acc = qgb2[t];
    for (int k = 0; k < H; k++) acc += h_s[k] * qgW2[t * H + k];
    qy_s[t] = acc;
    __syncthreads();
    acc = bq[t];
    for (int k = 0; k < H; k++) acc += qy_s[k] * Wq[t * H + k];
    q_s[t] = acc;
    __syncthreads();
#pragma unroll
    for (int hh = 0; hh < NH; hh++) {
        float u = 0.0f;
        for (int d = 0; d < 64; d++) u += q_s[hh * 64 + d] * Wk[(hh * 64 + d) * H + t];
        g_U[hh * H + t] = u * 0.125f;
    }
    if (t < NH) {
        float c = 0.0f;
        for (int d = 0; d < 64; d++) c += q_s[t * 64 + d] * bk[t * 64 + d];
        g_c[t] = c * 0.125f;
    }
}

// ---------------- cp.async chunk: [256n x 32k] hi+lo -> one B ring buffer --------
__device__ __forceinline__ void issue_chunk(const __nv_bfloat16* imgHi, const __nv_bfloat16* imgLo,
                                            int c, unsigned bufB, int tid) {
#pragma unroll
    for (int it = 0; it < 4; it++) {
        int flat = it * 512 + tid;               // 0..2047
        int mat = flat >> 10;                    // 0 hi, 1 lo
        int rem = flat & 1023;
        int n = rem >> 2, cg = rem & 3;
        const __nv_bfloat16* src = (mat ? imgLo : imgHi) + n * 256 + c * 32 + cg * 8;
        unsigned dst = bufB + mat * B_MATSZ + (unsigned)(n * BS + cg * 8) * 2;
        asm volatile("cp.async.cg.shared.global [%0], [%1], 16;" :: "r"(dst), "l"(src));
    }
    asm volatile("cp.async.commit_group;" ::: "memory");
}

// ---------------- one MLP layer: D[128,256] += A(hi+lo) @ W(hi+lo)^T -------------
__device__ __forceinline__ void run_layer(float (&acc)[2][8][4],
                                          const __nv_bfloat16* imgHi, const __nv_bfloat16* imgLo,
                                          unsigned aHiL, unsigned aLoL, unsigned bL,
                                          unsigned sbB, int tid) {
#pragma unroll 1
    for (int c = 0; c < 8; c++) {
        cp_wait0();
        __syncthreads();
        if (c < 7) issue_chunk(imgHi, imgLo, c + 1, sbB + ((c + 1) & 1) * B_BUFSZ, tid);
        unsigned bufB = sbB + (c & 1) * B_BUFSZ;
        int ka = c * 32;
#pragma unroll
        for (int ks = 0; ks < 2; ks++) {
            int kg = (ka + ks * 16) * 2;
            unsigned Ah0[4], Ah1[4], Al0[4], Al1[4];
            ldsm4(Ah0, aHiL + kg);
            ldsm4(Ah1, aHiL + kg + 16 * AS * 2);
            ldsm4(Al0, aLoL + kg);
            ldsm4(Al1, aLoL + kg + 16 * AS * 2);
#pragma unroll
            for (int ng = 0; ng < 2; ng++) {
                unsigned Bh[8], Bl[8];
                unsigned bo = bufB + bL + (unsigned)(ng * 32 * BS + ks * 16) * 2;
                ldsm4(Bh + 0, bo);
                ldsm4(Bh + 4, bo + 16 * BS * 2);
                ldsm4(Bl + 0, bo + B_MATSZ);
                ldsm4(Bl + 4, bo + B_MATSZ + 16 * BS * 2);
#pragma unroll
                for (int mt = 0; mt < 2; mt++) {
                    const unsigned* Ah = mt ? Ah1 : Ah0;
                    const unsigned* Al = mt ? Al1 : Al0;
#pragma unroll
                    for (int nt = 0; nt < 4; nt++) {
                        int bi = (nt >> 1) * 4 + (nt & 1);
                        unsigned bh0 = Bh[bi], bh1 = Bh[bi + 2];
                        unsigned bl0 = Bl[bi], bl1 = Bl[bi + 2];
                        float* cc = acc[mt][ng * 4 + nt];
                        mma16816(cc, Ah, bh0, bh1);
                        mma16816(cc, Al, bh0, bh1);
                        mma16816(cc, Ah, bl0, bl1);
                    }
                }
            }
        }
    }
}

// ---------------- main fused kernel -----------------------------------------------
__global__ __launch_bounds__(512, 1)
void k_mlp_main(const float* __restrict__ qubit_emb, const float* __restrict__ gate_emb,
                const int* __restrict__ map_qubit, const int* __restrict__ map_qpu,
                const int* __restrict__ sched_gate, const int* __restrict__ sched_time,
                const float* __restrict__ map_b1, const float* __restrict__ map_b2,
                const float* __restrict__ sch_b1, const float* __restrict__ sch_b2) {
    extern __shared__ unsigned char smem[];
    char* basep = (char*)smem;
    unsigned sb = smem_u32(smem);

    int tid = threadIdx.x;
    int lane = tid & 31, w = tid >> 5;
    int mq = w & 3, nq = w >> 2;                 // warp tile: 32m x 64n
    int rowbase = blockIdx.x * 128;
    bool is_map = rowbase < A_MAP;
    int lr0 = is_map ? rowbase : rowbase - A_MAP;
    const float* emb = is_map ? qubit_emb : gate_emb;
    const int* idx1g = is_map ? map_qubit : sched_gate;
    const int* idx2g = is_map ? map_qpu : sched_time;
    const float* contrib = is_map ? g_qpu_contrib : g_time_contrib;
    const float* b1 = is_map ? map_b1 : sch_b1;
    const float* b2 = is_map ? map_b2 : sch_b2;
    const __nv_bfloat16* img1hi = is_map ? g_W1m_hi : g_W1s_hi;
    const __nv_bfloat16* img1lo = is_map ? g_W1m_lo : g_W1s_lo;
    const __nv_bfloat16* img2hi = is_map ? g_W2m_hi : g_W2s_hi;
    const __nv_bfloat16* img2lo = is_map ? g_W2m_lo : g_W2s_lo;

    int* idx1_s = (int*)(basep + ST_OFF + ST_IDX1);
    int* idx2_s = (int*)(basep + ST_OFF + ST_IDX2);
    float* b1_s = (float*)(basep + ST_OFF + ST_B1);
    float* b2_s = (float*)(basep + ST_OFF + ST_B2);
    float* U_s  = (float*)(basep + ST_OFF + ST_U);
    float* c_s  = (float*)(basep + ST_OFF + ST_C);
    float* P_s  = (float*)(basep + ST_OFF + ST_P);
    unsigned* smx_s = (unsigned*)(basep + ST_OFF + ST_SMX);

    // prefetch layer-1 chunk 0 immediately
    issue_chunk(img1hi, img1lo, 0, sb + B_OFF, tid);

    if (tid < 128) { idx1_s[tid] = idx1g[lr0 + tid]; idx2_s[tid] = idx2g[lr0 + tid]; }
    if (tid < 256) { b1_s[tid] = b1[tid]; b2_s[tid] = b2[tid]; }
#pragma unroll
    for (int i = 0; i < 2; i++) U_s[i * 512 + tid] = g_U[i * 512 + tid];
    if (tid < NH) { c_s[tid] = g_c[tid]; smx_s[tid] = 0x007FFFFFu; }
    __syncthreads();

    // gather X [128 x 256] fp32 -> split into A hi/lo smem
#pragma unroll 1
    for (int i = 0; i < 16; i++) {
        int flat = i * 512 + tid;      // 128 rows x 64 float4
        int r = flat >> 6, c4 = flat & 63;
        float4 v = ((const float4*)(emb + (size_t)idx1_s[r] * H))[c4];
        unsigned short h0, l0, h1, l1, h2, l2, h3, l3;
        cvt_hilo(v.x, h0, l0); cvt_hilo(v.y, h1, l1);
        cvt_hilo(v.z, h2, l2); cvt_hilo(v.w, h3, l3);
        unsigned off = (unsigned)(r * AS + c4 * 4) * 2;
        *(uint2*)(basep + A_HI_OFF + off) = make_uint2((unsigned)h0 | ((unsigned)h1 << 16), (unsigned)h2 | ((unsigned)h3 << 16));
        *(uint2*)(basep + A_LO_OFF + off) = make_uint2((unsigned)l0 | ((unsigned)l1 << 16), (unsigned)l2 | ((unsigned)l3 << 16));
    }
    __syncthreads();

    // lane-based ldmatrix base addresses
    int g8 = lane >> 3, lr8 = lane & 7;
    int arow = mq * 32 + lr8 + ((g8 & 1) ? 8 : 0);
    int acol = (g8 & 2) ? 8 : 0;
    unsigned aHiL = sb + A_HI_OFF + (unsigned)(arow * AS + acol) * 2;
    unsigned aLoL = sb + A_LO_OFF + (unsigned)(arow * AS + acol) * 2;
    int brow = nq * 64 + lr8 + ((g8 & 1) ? 8 : 0);
    unsigned bL = (unsigned)(brow * BS + acol) * 2;

    float acc[2][8][4];
#pragma unroll
    for (int a = 0; a < 2; a++)
#pragma unroll
        for (int b = 0; b < 8; b++)
#pragma unroll
            for (int d = 0; d < 4; d++) acc[a][b][d] = 0.0f;

    int q4 = lane >> 2, lq = lane & 3;

    // ---- layer 1 ----
    run_layer(acc, img1hi, img1lo, aHiL, aLoL, bL, sb + B_OFF, tid);
    __syncthreads();
    issue_chunk(img2hi, img2lo, 0, sb + B_OFF, tid);   // prefetch L2 chunk0 over epi1

    // ---- epilogue 1: h = relu(D + contrib + b1) -> back into A hi/lo ------------
#pragma unroll
    for (int mt = 0; mt < 2; mt++)
#pragma unroll
        for (int hl = 0; hl < 2; hl++) {
            int row = mq * 32 + mt * 16 + q4 + hl * 8;
            const float* crow = contrib + (size_t)idx2_s[row] * H;
#pragma unroll
            for (int ntg = 0; ntg < 8; ntg++) {
                int col = nq * 64 + ntg * 8 + 2 * lq;
                float2 cv = *(const float2*)(crow + col);
                float v0 = fmaxf(acc[mt][ntg][hl * 2 + 0] + cv.x + b1_s[col], 0.0f);
                float v1 = fmaxf(acc[mt][ntg][hl * 2 + 1] + cv.y + b1_s[col + 1], 0.0f);
                unsigned short h0, l0, h1, l1;
                cvt_hilo(v0, h0, l0); cvt_hilo(v1, h1, l1);
                unsigned off = (unsigned)(row * AS + col) * 2;
                *(unsigned*)(basep + A_HI_OFF + off) = (unsigned)h0 | ((unsigned)h1 << 16);
                *(unsigned*)(basep + A_LO_OFF + off) = (unsigned)l0 | ((unsigned)l1 << 16);
                acc[mt][ntg][hl * 2 + 0] = 0.0f;
                acc[mt][ntg][hl * 2 + 1] = 0.0f;
            }
        }
    P_s[tid] = c_s[tid & 3];   // init score accumulators (128 rows x 4 heads)
    __syncthreads();

    // ---- layer 2 ----
    run_layer(acc, img2hi, img2lo, aHiL, aLoL, bL, sb + B_OFF, tid);
    __syncthreads();

    // ---- epilogue 2: keys = D + b2 -> gmem direct; fold score dots ---------------
    {
        float sd[2][2][NH];
#pragma unroll
        for (int mt = 0; mt < 2; mt++)
#pragma unroll
            for (int hl = 0; hl < 2; hl++)
#pragma unroll
                for (int hh = 0; hh < NH; hh++) sd[mt][hl][hh] = 0.0f;
#pragma unroll
        for (int mt = 0; mt < 2; mt++)
#pragma unroll
            for (int hl = 0; hl < 2; hl++) {
                int row = mq * 32 + mt * 16 + q4 + hl * 8;
                float* krow = g_keys + (size_t)(rowbase + row) * H;
#pragma unroll
                for (int ntg = 0; ntg < 8; ntg++) {
                    int col = nq * 64 + ntg * 8 + 2 * lq;
                    float v0 = acc[mt][ntg][hl * 2 + 0] + b2_s[col];
                    float v1 = acc[mt][ntg][hl * 2 + 1] + b2_s[col + 1];
                    *(float2*)(krow + col) = make_float2(v0, v1);
#pragma unroll
                    for (int hh = 0; hh < NH; hh++)
                        sd[mt][hl][hh] += v0 * U_s[hh * 256 + col] + v1 * U_s[hh * 256 + col + 1];
                }
            }
        // reduce over the quad (cols), then across nq warps via smem atomics
#pragma unroll
        for (int mt = 0; mt < 2; mt++)
#pragma unroll
            for (int hl = 0; hl < 2; hl++)
#pragma unroll
                for (int hh = 0; hh < NH; hh++) {
                    float s = sd[mt][hl][hh];
                    s += __shfl_xor_sync(0xffffffffu, s, 1);
                    s += __shfl_xor_sync(0xffffffffu, s, 2);
                    if (lq == 0) {
                        int row = mq * 32 + mt * 16 + q4 + hl * 8;
                        atomicAdd(&P_s[row * 4 + hh], s);
                    }
                }
    }
    __syncthreads();
    {
        int row = tid >> 2, hh = tid & 3;
        float s = P_s[tid];
        g_scores[(size_t)hh * A_TOT + rowbase + row] = s;
        atomicMax(&smx_s[hh], f2ord(s));
    }
    __syncthreads();
    if (tid < NH) atomicMax(&g_smax[tid], smx_s[tid]);
}

// ---------------- pass 2: softmax weights, weighted key-sum (cvec), expsum -------
__global__ void k_attn_acc() {
    __shared__ float w_s[NH * 256];
    __shared__ float red_s[NH * 8];
    int tid = threadIdx.x;
    size_t base = (size_t)blockIdx.x * 256;
    float sm[NH];
#pragma unroll
    for (int hh = 0; hh < NH; hh++) sm[hh] = ord2f(g_smax[hh]);
    float es[NH];
#pragma unroll
    for (int hh = 0; hh < NH; hh++) {
        float s = g_scores[(size_t)hh * A_TOT + base + tid];
        float wv = __expf(s - sm[hh]);
        w_s[hh * 256 + tid] = wv;
        es[hh] = wv;
    }
    __syncthreads();
    float cv0 = 0, cv1 = 0, cv2 = 0, cv3 = 0;
    for (int r = 0; r < 256; r++) {
        float kj = g_keys[(base + r) * H + tid];
        cv0 += w_s[r] * kj;
        cv1 += w_s[256 + r] * kj;
        cv2 += w_s[512 + r] * kj;
        cv3 += w_s[768 + r] * kj;
    }
    atomicAdd(&g_cvec[0 * H + tid], cv0);
    atomicAdd(&g_cvec[1 * H + tid], cv1);
    atomicAdd(&g_cvec[2 * H + tid], cv2);
    atomicAdd(&g_cvec[3 * H + tid], cv3);
#pragma unroll
    for (int hh = 0; hh < NH; hh++)
        for (int off = 16; off; off >>= 1) es[hh] += __shfl_down_sync(0xffffffffu, es[hh], off);
    if ((tid & 31) == 0) {
        int w = tid >> 5;
#pragma unroll
        for (int hh = 0; hh < NH; hh++) red_s[hh * 8 + w] = es[hh];
    }
    __syncthreads();
    if (tid < NH) {
        float s = 0.0f;
#pragma unroll
        for (int w = 0; w < 8; w++) s += red_s[tid * 8 + w];
        atomicAdd(&g_expsum[tid], s);
    }
}

// ---------------- ctx -> attn_out ------------------------------------------------
__global__ void k_ctx(const float* __restrict__ Wv, const float* __restrict__ bv,
                      const float* __restrict__ Wo, const float* __restrict__ bo) {
    __shared__ float ctx_s[H];
    int t = threadIdx.x;
    int hh = t >> 6;
    float inv = 1.0f / g_expsum[hh];
    float acc = 0.0f;
    for (int j = 0; j < H; j++) acc += Wv[t * H + j] * g_cvec[hh * H + j];
    ctx_s[t] = acc * inv + bv[t];
    __syncthreads();
    float o = bo[t];
    for (int j = 0; j < H; j++) o += Wo[t * H + j] * ctx_s[j];
    g_attn_out[t] = o;
}

// ---------------- logits = keys @ attn_out, track max ----------------------------
__global__ void k_logits() {
    __shared__ float ao_s[H];
    __shared__ float m_s[64];
    int tid = threadIdx.x;
    ao_s[tid] = g_attn_out[tid];
    __syncthreads();
    int r = tid >> 2, q4 = tid & 3;
    size_t a = (size_t)blockIdx.x * 64 + r;
    const float4* kp = (const float4*)(g_keys + a * H + q4 * 64);
    const float4* ap = (const float4*)(ao_s + q4 * 64);
    float p = 0.0f;
#pragma unroll
    for (int u = 0; u < 16; u++) {
        float4 kv = kp[u];
        float4 av = ap[u];
        p += kv.x * av.x + kv.y * av.y + kv.z * av.z + kv.w * av.w;
    }
    p += __shfl_down_sync(0xffffffffu, p, 2);
    p += __shfl_down_sync(0xffffffffu, p, 1);
    if (q4 == 0) { g_logits[a] = p; m_s[r] = p; }
    __syncthreads();
    if (tid < 32) {
        float m = fmaxf(m_s[tid], m_s[tid + 32]);
        for (int off = 16; off; off >>= 1) m = fmaxf(m, __shfl_down_sync(0xffffffffu, m, off));
        if (tid == 0) atomicMax(&g_lmax, f2ord(m));
    }
}

// ---------------- softmax denominator over logits --------------------------------
__global__ void k_lsum() {
    __shared__ float r_s[256];
    float lmax = ord2f(g_lmax);
    float s = 0.0f;
    for (int i = blockIdx.x * 256 + threadIdx.x; i < A_TOT; i += 256 * 256)
        s += __expf(g_logits[i] - lmax);
    r_s[threadIdx.x] = s;
    __syncthreads();
    for (int off = 128; off; off >>= 1) {
        if (threadIdx.x < off) r_s[threadIdx.x] += r_s[threadIdx.x + off];
        __syncthreads();
    }
    if (threadIdx.x == 0) atomicAdd(&g_lsum, r_s[0]);
}

// ---------------- write probs (+ logits) to output -------------------------------
__global__ void k_probs(float* __restrict__ out, int write_logits) {
    int i = blockIdx.x * 256 + threadIdx.x;
    float lmax = ord2f(g_lmax);
    float l = g_logits[i];
    out[i] = __expf(l - lmax) / g_lsum;
    if (write_logits) out[A_TOT + i] = l;
}

// ---------------- launch ----------------------------------------------------------
extern "C" void kernel_launch(void* const* d_in, const int* in_sizes, int n_in,
                              void* d_out, int out_size) {
    const float* qubit_emb = (const float*)d_in[0];
    const float* qpu_emb   = (const float*)d_in[1];
    const float* gate_emb  = (const float*)d_in[2];
    const float* all_emb   = (const float*)d_in[3];
    const float* time_tab  = (const float*)d_in[4];
    const float* map_W1 = (const float*)d_in[5];
    const float* map_b1 = (const float*)d_in[6];
    const float* map_W2 = (const float*)d_in[7];
    const float* map_b2 = (const float*)d_in[8];
    const float* sch_W1 = (const float*)d_in[9];
    const float* sch_b1 = (const float*)d_in[10];
    const float* sch_W2 = (const float*)d_in[11];
    const float* sch_b2 = (const float*)d_in[12];
    const float* qg_W1 = (const float*)d_in[13];
    const float* qg_b1 = (const float*)d_in[14];
    const float* qg_W2 = (const float*)d_in[15];
    const float* qg_b2 = (const float*)d_in[16];
    const float* attn_Wq = (const float*)d_in[17];
    const float* attn_bq = (const float*)d_in[18];
    const float* attn_Wk = (const float*)d_in[19];
    const float* attn_bk = (const float*)d_in[20];
    const float* attn_Wv = (const float*)d_in[21];
    const float* attn_bv = (const float*)d_in[22];
    const float* attn_Wo = (const float*)d_in[23];
    const float* attn_bo = (const float*)d_in[24];
    const int* map_qubit  = (const int*)d_in[25];
    const int* map_qpu    = (const int*)d_in[26];
    const int* sched_gate = (const int*)d_in[27];
    const int* sched_time = (const int*)d_in[28];
    float* out = (float*)d_out;
    int write_logits = (out_size >= 2 * A_TOT) ? 1 : 0;

    cudaFuncSetAttribute(k_mlp_main, cudaFuncAttributeMaxDynamicSharedMemorySize, DYN_SMEM);

    // launch order keeps k_mlp_main at position 6 so ncu (-s 5 -c 1) captures it
    k_wprep<<<1024, 64>>>(map_W1, sch_W1, map_W2, sch_W2);
    k_transpose<<<dim3(64, 2), dim3(32, 8)>>>(map_W1, sch_W1);
    k_mean<<<512, 256>>>(all_emb);
    k_contrib<<<67, 256>>>(qpu_emb, time_tab);
    k_small<<<1, 256>>>(qg_W1, qg_b1, qg_W2, qg_b2, attn_Wq, attn_bq, attn_Wk, attn_bk);
    k_mlp_main<<<2048, 512, DYN_SMEM>>>(qubit_emb, gate_emb, map_qubit, map_qpu,
                                        sched_gate, sched_time,
                                        map_b1, map_b2, sch_b1, sch_b2);
    k_attn_acc<<<1024, 256>>>();
    k_ctx<<<1, 256>>>(attn_Wv, attn_bv, attn_Wo, attn_bo);
    k_logits<<<4096, 256>>>();
    k_lsum<<<256, 256>>>();
    k_probs<<<1024, 256>>>(out, write_logits);
}